// round 16
// baseline (speedup 1.0000x reference)
#include <cuda_runtime.h>
#include <cstdint>

// Problem shapes (fixed by the dataset)
#define BB 4
#define CC 256
#define CO 32
#define NN 4096   // H*W = 64*64

// Scratch (allocation-free rule: __device__ globals)
__device__ float g_q[BB * CO * NN];                 // 2 MB
__device__ float g_k[BB * CO * NN];                 // 2 MB  (pre-scaled by log2 e)
__device__ float g_v[(size_t)BB * CC * NN];         // 16 MB (becomes v * rinv)
__device__ float g_e[(size_t)BB * NN * NN];         // 268 MB: exp(score)
__device__ float g_psum[(size_t)BB * 32 * NN];      // per-(b, mtile, n) tile sumexp
__device__ float g_rinv[BB * NN];                   // per-row 1/sum

#define LOG2E 1.44269504088896340736f

// ---------------------------------------------------------------------------
// helpers
// ---------------------------------------------------------------------------
__device__ __forceinline__ void mma_tf32_16x8x8(
    float c[4], const uint32_t a[4], const uint32_t b[2])
{
    asm volatile(
        "mma.sync.aligned.m16n8k8.row.col.f32.tf32.tf32.f32 "
        "{%0,%1,%2,%3}, {%4,%5,%6,%7}, {%8,%9}, {%0,%1,%2,%3};"
        : "+f"(c[0]), "+f"(c[1]), "+f"(c[2]), "+f"(c[3])
        : "r"(a[0]), "r"(a[1]), "r"(a[2]), "r"(a[3]),
          "r"(b[0]), "r"(b[1]));
}

__device__ __forceinline__ void cp_async16(uint32_t smem_dst, const void* gsrc) {
    asm volatile("cp.async.ca.shared.global [%0], [%1], 16;\n"
                 :: "r"(smem_dst), "l"(gsrc));
}
__device__ __forceinline__ void cp_commit() {
    asm volatile("cp.async.commit_group;\n" ::: "memory");
}
template <int N>
__device__ __forceinline__ void cp_wait() {
    asm volatile("cp.async.wait_group %0;\n" :: "n"(N) : "memory");
}

// ---------------------------------------------------------------------------
// Kernel 1: q/k projection.  k is pre-scaled by log2(e) (k only feeds scores).
// ---------------------------------------------------------------------------
__global__ __launch_bounds__(256) void qk_proj(
    const float* __restrict__ x,
    const float* __restrict__ Wq, const float* __restrict__ bq,
    const float* __restrict__ Wk, const float* __restrict__ bk)
{
    const int b  = blockIdx.y;
    const int n0 = blockIdx.x * 128;

    __shared__ float xs[32][128];
    __shared__ float wqs[32][32];
    __shared__ float wks[32][32];

    const int tid = threadIdx.x;
    const int nl  = tid & 127;
    const int oh  = tid >> 7;

    float accq[16], acck[16];
    #pragma unroll
    for (int r = 0; r < 16; r++) { accq[r] = 0.f; acck[r] = 0.f; }

    const float* xb = x + (size_t)b * CC * NN;

    for (int c0 = 0; c0 < CC; c0 += 32) {
        for (int i = tid; i < 32 * 128; i += 256) {
            int cc = i >> 7, nn = i & 127;
            xs[cc][nn] = xb[(size_t)(c0 + cc) * NN + n0 + nn];
        }
        for (int i = tid; i < 32 * 32; i += 256) {
            int o = i >> 5, cc = i & 31;
            wqs[cc][o] = Wq[o * CC + c0 + cc];
            wks[cc][o] = Wk[o * CC + c0 + cc];
        }
        __syncthreads();
        #pragma unroll
        for (int kk = 0; kk < 32; kk++) {
            float xv = xs[kk][nl];
            #pragma unroll
            for (int r = 0; r < 16; r++) {
                accq[r] += wqs[kk][oh * 16 + r] * xv;
                acck[r] += wks[kk][oh * 16 + r] * xv;
            }
        }
        __syncthreads();
    }
    #pragma unroll
    for (int r = 0; r < 16; r++) {
        int o = oh * 16 + r;
        g_q[((size_t)b * CO + o) * NN + n0 + nl] = accq[r] + bq[o];
        g_k[((size_t)b * CO + o) * NN + n0 + nl] = (acck[r] + bk[o]) * LOG2E;
    }
}

// ---------------------------------------------------------------------------
// tf32 GEMM template constants
// ---------------------------------------------------------------------------
#define AS_PITCH 36
#define BS_PITCH 132
#define AS_STAGE (128 * AS_PITCH)
#define BS_STAGE (32 * BS_PITCH)
#define SMEM_GEMM ((2 * AS_STAGE + 2 * BS_STAGE) * sizeof(float))

// ---------------------------------------------------------------------------
// Kernel 2 (FAT): blocks [0,256): v_proj tf32 (no rinv fold)
//                 blocks [256, 256+4096): scores -> exp2(score') into g_e
// ---------------------------------------------------------------------------
__global__ __launch_bounds__(256) void fat_scores_vproj(
    const float* __restrict__ x,
    const float* __restrict__ Wv, const float* __restrict__ bv)
{
    extern __shared__ float smem[];
    const int gid = blockIdx.x;
    const int tid = threadIdx.x;

    if (gid < 256) {
        // ---------------- v_proj path ----------------
        float* As = smem;
        float* Bs = smem + 2 * AS_STAGE;

        const int vid = gid;
        const int b  = vid >> 6;                // 0..3
        const int c0 = (vid & 1) * 128;
        const int n0 = ((vid & 63) >> 1) * 128;

        const float* xb = x + (size_t)b * CC * NN;

        const int lane = tid & 31;
        const int w    = tid >> 5;
        const int wc   = w >> 2;
        const int wm   = w & 3;

        const uint32_t as_base = (uint32_t)__cvta_generic_to_shared(As);
        const uint32_t bs_base = (uint32_t)__cvta_generic_to_shared(Bs);

        const int a_row = tid >> 1;
        const int a_c4  = (tid & 1) * 16;
        const int b_kr  = tid >> 3;
        const int b_m4  = (tid & 7) * 16;

        auto load_stage = [&](int s, int k0) {
            const float* ga = &Wv[(c0 + a_row) * CC + k0 + a_c4];
            uint32_t da = as_base + (s * AS_STAGE + a_row * AS_PITCH + a_c4) * 4;
            cp_async16(da,      ga);
            cp_async16(da + 16, ga + 4);
            cp_async16(da + 32, ga + 8);
            cp_async16(da + 48, ga + 12);
            const float* gb = &xb[(size_t)(k0 + b_kr) * NN + n0 + b_m4];
            uint32_t db = bs_base + (s * BS_STAGE + b_kr * BS_PITCH + b_m4) * 4;
            cp_async16(db,      gb);
            cp_async16(db + 16, gb + 4);
            cp_async16(db + 32, gb + 8);
            cp_async16(db + 48, gb + 12);
        };

        float acc[4][4][4];
        #pragma unroll
        for (int mi = 0; mi < 4; mi++)
            #pragma unroll
            for (int ni = 0; ni < 4; ni++)
                #pragma unroll
                for (int r = 0; r < 4; r++) acc[mi][ni][r] = 0.f;

        const int lq = lane >> 2;
        const int lr = lane & 3;

        load_stage(0, 0);
        cp_commit();

        for (int it = 0; it < CC / 32; it++) {
            const int s = it & 1;
            if (it + 1 < CC / 32) {
                load_stage(s ^ 1, (it + 1) * 32);
                cp_commit();
                cp_wait<1>();
            } else {
                cp_wait<0>();
            }
            __syncthreads();

            const float* Asl = As + s * AS_STAGE;
            const float* Bsl = Bs + s * BS_STAGE;

            #pragma unroll
            for (int kk = 0; kk < 32; kk += 8) {
                uint32_t af[4][4];
                #pragma unroll
                for (int mi = 0; mi < 4; mi++) {
                    int r = wc * 64 + mi * 16 + lq;
                    af[mi][0] = __float_as_uint(Asl[(r    ) * AS_PITCH + kk + lr    ]);
                    af[mi][1] = __float_as_uint(Asl[(r + 8) * AS_PITCH + kk + lr    ]);
                    af[mi][2] = __float_as_uint(Asl[(r    ) * AS_PITCH + kk + lr + 4]);
                    af[mi][3] = __float_as_uint(Asl[(r + 8) * AS_PITCH + kk + lr + 4]);
                }
                uint32_t bf[4][2];
                #pragma unroll
                for (int ni = 0; ni < 4; ni++) {
                    int m = wm * 32 + ni * 8 + lq;
                    bf[ni][0] = __float_as_uint(Bsl[(kk + lr    ) * BS_PITCH + m]);
                    bf[ni][1] = __float_as_uint(Bsl[(kk + lr + 4) * BS_PITCH + m]);
                }
                #pragma unroll
                for (int mi = 0; mi < 4; mi++)
                    #pragma unroll
                    for (int ni = 0; ni < 4; ni++)
                        mma_tf32_16x8x8(acc[mi][ni], af[mi], bf[ni]);
            }
            __syncthreads();
        }

        float* vbo = g_v + (size_t)b * CC * NN;

        #pragma unroll
        for (int mi = 0; mi < 4; mi++) {
            #pragma unroll
            for (int ni = 0; ni < 4; ni++) {
                int c = c0 + wc * 64 + mi * 16 + lq;
                int m = n0 + wm * 32 + ni * 8 + lr * 2;
                float bias0 = bv[c];
                float bias1 = bv[c + 8];
                {
                    size_t off = (size_t)c * NN + m;
                    float2 o;
                    o.x = acc[mi][ni][0] + bias0;
                    o.y = acc[mi][ni][1] + bias0;
                    *reinterpret_cast<float2*>(&vbo[off]) = o;
                }
                {
                    size_t off = (size_t)(c + 8) * NN + m;
                    float2 o;
                    o.x = acc[mi][ni][2] + bias1;
                    o.y = acc[mi][ni][3] + bias1;
                    *reinterpret_cast<float2*>(&vbo[off]) = o;
                }
            }
        }
        return;
    }

    // ---------------- scores path (exp2f) ----------------
    {
        const int sid = gid - 256;
        const int b   = sid >> 10;               // 0..3
        const int rem = sid & 1023;
        const int mt  = rem & 31;
        const int m0  = mt * 128;
        const int n0  = ((rem >> 5) & 31) * 128;

        float* ks = smem;                        // [32][128]
        float* qs = smem + CO * 128;             // [32][128]

        const float* kb = g_k + (size_t)b * CO * NN;
        const float* qb = g_q + (size_t)b * CO * NN;

        #pragma unroll
        for (int it = 0; it < 4; it++) {
            int idx = tid + it * 256;
            int row = idx >> 5;
            int c4  = (idx & 31) * 4;
            *reinterpret_cast<float4*>(&ks[row * 128 + c4]) =
                *reinterpret_cast<const float4*>(&kb[(size_t)row * NN + n0 + c4]);
            *reinterpret_cast<float4*>(&qs[row * 128 + c4]) =
                *reinterpret_cast<const float4*>(&qb[(size_t)row * NN + m0 + c4]);
        }
        __syncthreads();

        const int tx = tid & 15, ty = tid >> 4;
        float acc[8][8];
        #pragma unroll
        for (int r = 0; r < 8; r++)
            #pragma unroll
            for (int s = 0; s < 8; s++) acc[r][s] = 0.f;

        #pragma unroll
        for (int c = 0; c < CO; c++) {
            float4 a0 = *reinterpret_cast<const float4*>(&ks[c * 128 + ty * 8]);
            float4 a1 = *reinterpret_cast<const float4*>(&ks[c * 128 + ty * 8 + 4]);
            float4 b0 = *reinterpret_cast<const float4*>(&qs[c * 128 + tx * 8]);
            float4 b1 = *reinterpret_cast<const float4*>(&qs[c * 128 + tx * 8 + 4]);
            float ra[8] = {a0.x, a0.y, a0.z, a0.w, a1.x, a1.y, a1.z, a1.w};
            float rb[8] = {b0.x, b0.y, b0.z, b0.w, b1.x, b1.y, b1.z, b1.w};
            #pragma unroll
            for (int r = 0; r < 8; r++)
                #pragma unroll
                for (int s = 0; s < 8; s++) acc[r][s] += ra[r] * rb[s];
        }

        float rowsum[8];
        #pragma unroll
        for (int r = 0; r < 8; r++) {
            float sm = 0.f;
            #pragma unroll
            for (int s = 0; s < 8; s++) {
                float e = exp2f(acc[r][s]);
                acc[r][s] = e;
                sm += e;
            }
            #pragma unroll
            for (int o = 8; o; o >>= 1) sm += __shfl_xor_sync(0xffffffffu, sm, o);
            rowsum[r] = sm;
        }
        if (tx == 0) {
            size_t base = (((size_t)b * 32 + mt) << 12) + n0 + ty * 8;
            #pragma unroll
            for (int r = 0; r < 8; r++) g_psum[base + r] = rowsum[r];
        }

        float* ep = g_e + (size_t)b * NN * NN;
        #pragma unroll
        for (int r = 0; r < 8; r++) {
            size_t n = (size_t)(n0 + ty * 8 + r);
            #pragma unroll
            for (int s = 0; s < 8; s += 4) {
                float4 o;
                o.x = acc[r][s + 0]; o.y = acc[r][s + 1];
                o.z = acc[r][s + 2]; o.w = acc[r][s + 3];
                *reinterpret_cast<float4*>(&ep[n * NN + m0 + tx * 8 + s]) = o;
            }
        }
    }
}

// ---------------------------------------------------------------------------
// Kernel 3: combine 32 per-tile sums -> rinv = 1/sum
// ---------------------------------------------------------------------------
__global__ __launch_bounds__(128) void stats_reduce()
{
    const int b = blockIdx.y;
    const int n = blockIdx.x * 128 + threadIdx.x;

    float s = 0.f;
    #pragma unroll
    for (int mt = 0; mt < 32; mt++)
        s += g_psum[(((size_t)b * 32 + mt) << 12) + n];
    g_rinv[b * NN + n] = 1.0f / s;
}

// ---------------------------------------------------------------------------
// Kernel 4: fold rinv into v:  v[b,c,n] *= rinv[b,n]   (coalesced, ~8 us)
// ---------------------------------------------------------------------------
__global__ __launch_bounds__(256) void scale_v()
{
    const size_t i4 = (size_t)blockIdx.x * 256 + threadIdx.x;  // float4 index
    const size_t f  = i4 * 4;
    const int n = (int)(f & (NN - 1));
    const int b = (int)(f / ((size_t)CC * NN));

    float4 v = reinterpret_cast<float4*>(g_v)[i4];
    float4 r = reinterpret_cast<const float4*>(g_rinv)[(b * NN + n) >> 2];
    v.x *= r.x; v.y *= r.y; v.z *= r.z; v.w *= r.w;
    reinterpret_cast<float4*>(g_v)[i4] = v;
}

// ---------------------------------------------------------------------------
// Kernel 5 (FAT): blocks [0,256): out gemm; [256,512): normalize (64 rows each)
// __launch_bounds__(256, 3): cap regs at 85 so 3 blocks/SM fit (was 98 regs ->
// 2 blocks/SM, occ 22%, issue 13% -- latency-bound per R15 profile).
// ---------------------------------------------------------------------------
__global__ __launch_bounds__(256, 3) void gemm_norm_fused(
    const float* __restrict__ x,
    const float* __restrict__ gamma,
    float* __restrict__ out,
    float* __restrict__ attn)
{
    const int gid = blockIdx.x;

    if (gid >= 256) {
        // ---------------- normalize path (contiguous 64-row chunks) --------
        const int idx = gid - 256;                 // 0..255
        const int tid = threadIdx.x;
        #pragma unroll 1
        for (int r = 0; r < 64; r++) {
            size_t row = (size_t)idx * 64 + r;     // global row: b*NN + n
            const float rinv = g_rinv[row];
            const float4* src = reinterpret_cast<const float4*>(g_e + row * NN);
            float4* dst = reinterpret_cast<float4*>(attn + row * NN);
            #pragma unroll
            for (int j = 0; j < 4; j++) {
                int i = tid + j * 256;
                float4 v = src[i];
                v.x *= rinv; v.y *= rinv; v.z *= rinv; v.w *= rinv;
                dst[i] = v;
            }
        }
        return;
    }

    // ---------------- gemm path ----------------
    extern __shared__ float smem[];
    float* As = smem;
    float* Bs = smem + 2 * AS_STAGE;

    const int b  = gid >> 6;
    const int t  = gid & 63;
    const int c0 = (t & 1) * 128;
    const int m0 = (t >> 1) * 128;

    const float* vb = g_v + (size_t)b * CC * NN;
    const float* eb = g_e + (size_t)b * NN * NN;

    const int tid  = threadIdx.x;
    const int lane = tid & 31;
    const int w    = tid >> 5;
    const int wc   = w >> 2;
    const int wm   = w & 3;

    const uint32_t as_base = (uint32_t)__cvta_generic_to_shared(As);
    const uint32_t bs_base = (uint32_t)__cvta_generic_to_shared(Bs);

    const int a_row = tid >> 1;
    const int a_c4  = (tid & 1) * 16;
    const int b_kr  = tid >> 3;
    const int b_m4  = (tid & 7) * 16;

    auto load_stage = [&](int s, int k0) {
        const float* ga = &vb[(size_t)(c0 + a_row) * NN + k0 + a_c4];
        uint32_t da = as_base + (s * AS_STAGE + a_row * AS_PITCH + a_c4) * 4;
        cp_async16(da,      ga);
        cp_async16(da + 16, ga + 4);
        cp_async16(da + 32, ga + 8);
        cp_async16(da + 48, ga + 12);
        const float* gb = &eb[(size_t)(k0 + b_kr) * NN + m0 + b_m4];
        uint32_t db = bs_base + (s * BS_STAGE + b_kr * BS_PITCH + b_m4) * 4;
        cp_async16(db,      gb);
        cp_async16(db + 16, gb + 4);
        cp_async16(db + 32, gb + 8);
        cp_async16(db + 48, gb + 12);
    };

    float acc[4][4][4];
    #pragma unroll
    for (int mi = 0; mi < 4; mi++)
        #pragma unroll
        for (int ni = 0; ni < 4; ni++)
            #pragma unroll
            for (int r = 0; r < 4; r++) acc[mi][ni][r] = 0.f;

    const int lq = lane >> 2;
    const int lr = lane & 3;

    load_stage(0, 0);
    cp_commit();

    for (int it = 0; it < NN / 32; it++) {
        const int s = it & 1;
        if (it + 1 < NN / 32) {
            load_stage(s ^ 1, (it + 1) * 32);
            cp_commit();
            cp_wait<1>();
        } else {
            cp_wait<0>();
        }
        __syncthreads();

        const float* Asl = As + s * AS_STAGE;
        const float* Bsl = Bs + s * BS_STAGE;

        #pragma unroll
        for (int kk = 0; kk < 32; kk += 8) {
            uint32_t af[4][4];
            #pragma unroll
            for (int mi = 0; mi < 4; mi++) {
                int r = wc * 64 + mi * 16 + lq;
                af[mi][0] = __float_as_uint(Asl[(r    ) * AS_PITCH + kk + lr    ]);
                af[mi][1] = __float_as_uint(Asl[(r + 8) * AS_PITCH + kk + lr    ]);
                af[mi][2] = __float_as_uint(Asl[(r    ) * AS_PITCH + kk + lr + 4]);
                af[mi][3] = __float_as_uint(Asl[(r + 8) * AS_PITCH + kk + lr + 4]);
            }
            uint32_t bf[4][2];
            #pragma unroll
            for (int ni = 0; ni < 4; ni++) {
                int m = wm * 32 + ni * 8 + lq;
                bf[ni][0] = __float_as_uint(Bsl[(kk + lr    ) * BS_PITCH + m]);
                bf[ni][1] = __float_as_uint(Bsl[(kk + lr + 4) * BS_PITCH + m]);
            }
            #pragma unroll
            for (int mi = 0; mi < 4; mi++)
                #pragma unroll
                for (int ni = 0; ni < 4; ni++)
                    mma_tf32_16x8x8(acc[mi][ni], af[mi], bf[ni]);
        }
        __syncthreads();
    }

    const float g = __ldg(gamma);
    const float* xb = x + (size_t)b * CC * NN;
    float* ob = out + (size_t)b * CC * NN;

    #pragma unroll
    for (int mi = 0; mi < 4; mi++) {
        #pragma unroll
        for (int ni = 0; ni < 4; ni++) {
            int c = c0 + wc * 64 + mi * 16 + lq;
            int m = m0 + wm * 32 + ni * 8 + lr * 2;
            {
                size_t off = (size_t)c * NN + m;
                float2 xr = *reinterpret_cast<const float2*>(&xb[off]);
                float2 o;
                o.x = g * acc[mi][ni][0] + xr.x;
                o.y = g * acc[mi][ni][1] + xr.y;
                *reinterpret_cast<float2*>(&ob[off]) = o;
            }
            {
                size_t off = (size_t)(c + 8) * NN + m;
                float2 xr = *reinterpret_cast<const float2*>(&xb[off]);
                float2 o;
                o.x = g * acc[mi][ni][2] + xr.x;
                o.y = g * acc[mi][ni][3] + xr.y;
                *reinterpret_cast<float2*>(&ob[off]) = o;
            }
        }
    }
}

// ---------------------------------------------------------------------------
extern "C" void kernel_launch(void* const* d_in, const int* in_sizes, int n_in,
                              void* d_out, int out_size)
{
    (void)in_sizes; (void)n_in; (void)out_size;

    const float* x     = (const float*)d_in[0];
    const float* Wq    = (const float*)d_in[1];
    const float* bq    = (const float*)d_in[2];
    const float* Wk    = (const float*)d_in[3];
    const float* bk    = (const float*)d_in[4];
    const float* Wv    = (const float*)d_in[5];
    const float* bv    = (const float*)d_in[6];
    const float* gamma = (const float*)d_in[7];

    float* out  = (float*)d_out;                       // (B, C, H, W)
    float* attn = out + (size_t)BB * CC * NN;          // (B, N, N)

    static bool attr_set = false;
    if (!attr_set) {
        cudaFuncSetAttribute(fat_scores_vproj,
            cudaFuncAttributeMaxDynamicSharedMemorySize, (int)SMEM_GEMM);
        cudaFuncSetAttribute(gemm_norm_fused,
            cudaFuncAttributeMaxDynamicSharedMemorySize, (int)SMEM_GEMM);
        attr_set = true;
    }

    qk_proj         <<<dim3(NN / 128, BB), 256>>>(x, Wq, bq, Wk, bk);
    fat_scores_vproj<<<256 + BB * 32 * 32, 256, SMEM_GEMM>>>(x, Wv, bv);
    stats_reduce    <<<dim3(NN / 128, BB), 128>>>();
    scale_v         <<<(BB * CC * NN / 4) / 256, 256>>>();
    gemm_norm_fused <<<512, 256, SMEM_GEMM>>>(x, gamma, out, attn);
}

// round 17
// speedup vs baseline: 1.9164x; 1.9164x over previous
#include <cuda_runtime.h>
#include <cstdint>

// Problem shapes (fixed by the dataset)
#define BB 4
#define CC 256
#define CO 32
#define NN 4096   // H*W = 64*64

// Scratch (allocation-free rule: __device__ globals)
__device__ float g_q[BB * CO * NN];                 // 2 MB
__device__ float g_k[BB * CO * NN];                 // 2 MB  (pre-scaled by log2 e)
__device__ float g_v[(size_t)BB * CC * NN];         // 16 MB (becomes v * rinv)
__device__ float g_e[(size_t)BB * NN * NN];         // 268 MB: exp(score)
__device__ float g_psum[(size_t)BB * 32 * NN];      // per-(b, mtile, n) tile sumexp
__device__ float g_rinv[BB * NN];                   // per-row 1/sum

#define LOG2E 1.44269504088896340736f

// ---------------------------------------------------------------------------
// helpers
// ---------------------------------------------------------------------------
__device__ __forceinline__ void mma_tf32_16x8x8(
    float c[4], const uint32_t a[4], const uint32_t b[2])
{
    asm volatile(
        "mma.sync.aligned.m16n8k8.row.col.f32.tf32.tf32.f32 "
        "{%0,%1,%2,%3}, {%4,%5,%6,%7}, {%8,%9}, {%0,%1,%2,%3};"
        : "+f"(c[0]), "+f"(c[1]), "+f"(c[2]), "+f"(c[3])
        : "r"(a[0]), "r"(a[1]), "r"(a[2]), "r"(a[3]),
          "r"(b[0]), "r"(b[1]));
}

__device__ __forceinline__ void cp_async16(uint32_t smem_dst, const void* gsrc) {
    asm volatile("cp.async.ca.shared.global [%0], [%1], 16;\n"
                 :: "r"(smem_dst), "l"(gsrc));
}
__device__ __forceinline__ void cp_commit() {
    asm volatile("cp.async.commit_group;\n" ::: "memory");
}
template <int N>
__device__ __forceinline__ void cp_wait() {
    asm volatile("cp.async.wait_group %0;\n" :: "n"(N) : "memory");
}

// ---------------------------------------------------------------------------
// Kernel 1: q/k projection.  k is pre-scaled by log2(e).
// ---------------------------------------------------------------------------
__global__ __launch_bounds__(256) void qk_proj(
    const float* __restrict__ x,
    const float* __restrict__ Wq, const float* __restrict__ bq,
    const float* __restrict__ Wk, const float* __restrict__ bk)
{
    const int b  = blockIdx.y;
    const int n0 = blockIdx.x * 128;

    __shared__ float xs[32][128];
    __shared__ float wqs[32][32];
    __shared__ float wks[32][32];

    const int tid = threadIdx.x;
    const int nl  = tid & 127;
    const int oh  = tid >> 7;

    float accq[16], acck[16];
    #pragma unroll
    for (int r = 0; r < 16; r++) { accq[r] = 0.f; acck[r] = 0.f; }

    const float* xb = x + (size_t)b * CC * NN;

    for (int c0 = 0; c0 < CC; c0 += 32) {
        for (int i = tid; i < 32 * 128; i += 256) {
            int cc = i >> 7, nn = i & 127;
            xs[cc][nn] = xb[(size_t)(c0 + cc) * NN + n0 + nn];
        }
        for (int i = tid; i < 32 * 32; i += 256) {
            int o = i >> 5, cc = i & 31;
            wqs[cc][o] = Wq[o * CC + c0 + cc];
            wks[cc][o] = Wk[o * CC + c0 + cc];
        }
        __syncthreads();
        #pragma unroll
        for (int kk = 0; kk < 32; kk++) {
            float xv = xs[kk][nl];
            #pragma unroll
            for (int r = 0; r < 16; r++) {
                accq[r] += wqs[kk][oh * 16 + r] * xv;
                acck[r] += wks[kk][oh * 16 + r] * xv;
            }
        }
        __syncthreads();
    }
    #pragma unroll
    for (int r = 0; r < 16; r++) {
        int o = oh * 16 + r;
        g_q[((size_t)b * CO + o) * NN + n0 + nl] = accq[r] + bq[o];
        g_k[((size_t)b * CO + o) * NN + n0 + nl] = (acck[r] + bk[o]) * LOG2E;
    }
}

// ---------------------------------------------------------------------------
// tf32 GEMM template constants
// ---------------------------------------------------------------------------
#define AS_PITCH 36
#define BS_PITCH 132
#define AS_STAGE (128 * AS_PITCH)
#define BS_STAGE (32 * BS_PITCH)
#define SMEM_GEMM ((2 * AS_STAGE + 2 * BS_STAGE) * sizeof(float))

// ---------------------------------------------------------------------------
// Kernel 2 (FAT): blocks [0,256): v_proj tf32; [256,256+4096): scores/exp2.
// (exact R14 body — measured 633 total)
// ---------------------------------------------------------------------------
__global__ __launch_bounds__(256) void fat_scores_vproj(
    const float* __restrict__ x,
    const float* __restrict__ Wv, const float* __restrict__ bv)
{
    extern __shared__ float smem[];
    const int gid = blockIdx.x;
    const int tid = threadIdx.x;

    if (gid < 256) {
        // ---------------- v_proj path ----------------
        float* As = smem;
        float* Bs = smem + 2 * AS_STAGE;

        const int vid = gid;
        const int b  = vid >> 6;
        const int c0 = (vid & 1) * 128;
        const int n0 = ((vid & 63) >> 1) * 128;

        const float* xb = x + (size_t)b * CC * NN;

        const int lane = tid & 31;
        const int w    = tid >> 5;
        const int wc   = w >> 2;
        const int wm   = w & 3;

        const uint32_t as_base = (uint32_t)__cvta_generic_to_shared(As);
        const uint32_t bs_base = (uint32_t)__cvta_generic_to_shared(Bs);

        const int a_row = tid >> 1;
        const int a_c4  = (tid & 1) * 16;
        const int b_kr  = tid >> 3;
        const int b_m4  = (tid & 7) * 16;

        auto load_stage = [&](int s, int k0) {
            const float* ga = &Wv[(c0 + a_row) * CC + k0 + a_c4];
            uint32_t da = as_base + (s * AS_STAGE + a_row * AS_PITCH + a_c4) * 4;
            cp_async16(da,      ga);
            cp_async16(da + 16, ga + 4);
            cp_async16(da + 32, ga + 8);
            cp_async16(da + 48, ga + 12);
            const float* gb = &xb[(size_t)(k0 + b_kr) * NN + n0 + b_m4];
            uint32_t db = bs_base + (s * BS_STAGE + b_kr * BS_PITCH + b_m4) * 4;
            cp_async16(db,      gb);
            cp_async16(db + 16, gb + 4);
            cp_async16(db + 32, gb + 8);
            cp_async16(db + 48, gb + 12);
        };

        float acc[4][4][4];
        #pragma unroll
        for (int mi = 0; mi < 4; mi++)
            #pragma unroll
            for (int ni = 0; ni < 4; ni++)
                #pragma unroll
                for (int r = 0; r < 4; r++) acc[mi][ni][r] = 0.f;

        const int lq = lane >> 2;
        const int lr = lane & 3;

        load_stage(0, 0);
        cp_commit();

        for (int it = 0; it < CC / 32; it++) {
            const int s = it & 1;
            if (it + 1 < CC / 32) {
                load_stage(s ^ 1, (it + 1) * 32);
                cp_commit();
                cp_wait<1>();
            } else {
                cp_wait<0>();
            }
            __syncthreads();

            const float* Asl = As + s * AS_STAGE;
            const float* Bsl = Bs + s * BS_STAGE;

            #pragma unroll
            for (int kk = 0; kk < 32; kk += 8) {
                uint32_t af[4][4];
                #pragma unroll
                for (int mi = 0; mi < 4; mi++) {
                    int r = wc * 64 + mi * 16 + lq;
                    af[mi][0] = __float_as_uint(Asl[(r    ) * AS_PITCH + kk + lr    ]);
                    af[mi][1] = __float_as_uint(Asl[(r + 8) * AS_PITCH + kk + lr    ]);
                    af[mi][2] = __float_as_uint(Asl[(r    ) * AS_PITCH + kk + lr + 4]);
                    af[mi][3] = __float_as_uint(Asl[(r + 8) * AS_PITCH + kk + lr + 4]);
                }
                uint32_t bf[4][2];
                #pragma unroll
                for (int ni = 0; ni < 4; ni++) {
                    int m = wm * 32 + ni * 8 + lq;
                    bf[ni][0] = __float_as_uint(Bsl[(kk + lr    ) * BS_PITCH + m]);
                    bf[ni][1] = __float_as_uint(Bsl[(kk + lr + 4) * BS_PITCH + m]);
                }
                #pragma unroll
                for (int mi = 0; mi < 4; mi++)
                    #pragma unroll
                    for (int ni = 0; ni < 4; ni++)
                        mma_tf32_16x8x8(acc[mi][ni], af[mi], bf[ni]);
            }
            __syncthreads();
        }

        float* vbo = g_v + (size_t)b * CC * NN;

        #pragma unroll
        for (int mi = 0; mi < 4; mi++) {
            #pragma unroll
            for (int ni = 0; ni < 4; ni++) {
                int c = c0 + wc * 64 + mi * 16 + lq;
                int m = n0 + wm * 32 + ni * 8 + lr * 2;
                float bias0 = bv[c];
                float bias1 = bv[c + 8];
                {
                    size_t off = (size_t)c * NN + m;
                    float2 o;
                    o.x = acc[mi][ni][0] + bias0;
                    o.y = acc[mi][ni][1] + bias0;
                    *reinterpret_cast<float2*>(&vbo[off]) = o;
                }
                {
                    size_t off = (size_t)(c + 8) * NN + m;
                    float2 o;
                    o.x = acc[mi][ni][2] + bias1;
                    o.y = acc[mi][ni][3] + bias1;
                    *reinterpret_cast<float2*>(&vbo[off]) = o;
                }
            }
        }
        return;
    }

    // ---------------- scores path (exp2f) ----------------
    {
        const int sid = gid - 256;
        const int b   = sid >> 10;
        const int rem = sid & 1023;
        const int mt  = rem & 31;
        const int m0  = mt * 128;
        const int n0  = ((rem >> 5) & 31) * 128;

        float* ks = smem;
        float* qs = smem + CO * 128;

        const float* kb = g_k + (size_t)b * CO * NN;
        const float* qb = g_q + (size_t)b * CO * NN;

        #pragma unroll
        for (int it = 0; it < 4; it++) {
            int idx = tid + it * 256;
            int row = idx >> 5;
            int c4  = (idx & 31) * 4;
            *reinterpret_cast<float4*>(&ks[row * 128 + c4]) =
                *reinterpret_cast<const float4*>(&kb[(size_t)row * NN + n0 + c4]);
            *reinterpret_cast<float4*>(&qs[row * 128 + c4]) =
                *reinterpret_cast<const float4*>(&qb[(size_t)row * NN + m0 + c4]);
        }
        __syncthreads();

        const int tx = tid & 15, ty = tid >> 4;
        float acc[8][8];
        #pragma unroll
        for (int r = 0; r < 8; r++)
            #pragma unroll
            for (int s = 0; s < 8; s++) acc[r][s] = 0.f;

        #pragma unroll
        for (int c = 0; c < CO; c++) {
            float4 a0 = *reinterpret_cast<const float4*>(&ks[c * 128 + ty * 8]);
            float4 a1 = *reinterpret_cast<const float4*>(&ks[c * 128 + ty * 8 + 4]);
            float4 b0 = *reinterpret_cast<const float4*>(&qs[c * 128 + tx * 8]);
            float4 b1 = *reinterpret_cast<const float4*>(&qs[c * 128 + tx * 8 + 4]);
            float ra[8] = {a0.x, a0.y, a0.z, a0.w, a1.x, a1.y, a1.z, a1.w};
            float rb[8] = {b0.x, b0.y, b0.z, b0.w, b1.x, b1.y, b1.z, b1.w};
            #pragma unroll
            for (int r = 0; r < 8; r++)
                #pragma unroll
                for (int s = 0; s < 8; s++) acc[r][s] += ra[r] * rb[s];
        }

        float rowsum[8];
        #pragma unroll
        for (int r = 0; r < 8; r++) {
            float sm = 0.f;
            #pragma unroll
            for (int s = 0; s < 8; s++) {
                float e = exp2f(acc[r][s]);
                acc[r][s] = e;
                sm += e;
            }
            #pragma unroll
            for (int o = 8; o; o >>= 1) sm += __shfl_xor_sync(0xffffffffu, sm, o);
            rowsum[r] = sm;
        }
        if (tx == 0) {
            size_t base = (((size_t)b * 32 + mt) << 12) + n0 + ty * 8;
            #pragma unroll
            for (int r = 0; r < 8; r++) g_psum[base + r] = rowsum[r];
        }

        float* ep = g_e + (size_t)b * NN * NN;
        #pragma unroll
        for (int r = 0; r < 8; r++) {
            size_t n = (size_t)(n0 + ty * 8 + r);
            #pragma unroll
            for (int s = 0; s < 8; s += 4) {
                float4 o;
                o.x = acc[r][s + 0]; o.y = acc[r][s + 1];
                o.z = acc[r][s + 2]; o.w = acc[r][s + 3];
                *reinterpret_cast<float4*>(&ep[n * NN + m0 + tx * 8 + s]) = o;
            }
        }
    }
}

// ---------------------------------------------------------------------------
// Kernel 3: combine 32 per-tile sums -> rinv = 1/sum
// ---------------------------------------------------------------------------
__global__ __launch_bounds__(128) void stats_reduce()
{
    const int b = blockIdx.y;
    const int n = blockIdx.x * 128 + threadIdx.x;

    float s = 0.f;
    #pragma unroll
    for (int mt = 0; mt < 32; mt++)
        s += g_psum[(((size_t)b * 32 + mt) << 12) + n];
    g_rinv[b * NN + n] = 1.0f / s;
}

// ---------------------------------------------------------------------------
// Kernel 4: fold rinv into v (coalesced, ~8 us)
// ---------------------------------------------------------------------------
__global__ __launch_bounds__(256) void scale_v()
{
    const size_t i4 = (size_t)blockIdx.x * 256 + threadIdx.x;
    const size_t f  = i4 * 4;
    const int n = (int)(f & (NN - 1));
    const int b = (int)(f / ((size_t)CC * NN));

    float4 v = reinterpret_cast<float4*>(g_v)[i4];
    float4 r = reinterpret_cast<const float4*>(g_rinv)[(b * NN + n) >> 2];
    v.x *= r.x; v.y *= r.y; v.z *= r.z; v.w *= r.w;
    reinterpret_cast<float4*>(g_v)[i4] = v;
}

// ---------------------------------------------------------------------------
// Kernel 5 (FAT, 512 threads): blocks [0,256): out gemm (block tile 128x128,
// 16 warps as 4c x 4m, warp tile 32x32 -> acc 32 regs/thread, ~60-64 total ->
// 2 blocks/SM = 32 warps/SM, double the 256-thread variant).
// Blocks [256,512): normalize, 64 contiguous rows each.
// ---------------------------------------------------------------------------
__global__ __launch_bounds__(512, 2) void gemm_norm_fused(
    const float* __restrict__ x,
    const float* __restrict__ gamma,
    float* __restrict__ out,
    float* __restrict__ attn)
{
    const int gid = blockIdx.x;
    const int tid = threadIdx.x;

    if (gid >= 256) {
        // ---------------- normalize path ----------------
        const int idx = gid - 256;                 // 0..255
        #pragma unroll 1
        for (int r = 0; r < 64; r++) {
            size_t row = (size_t)idx * 64 + r;
            const float rinv = g_rinv[row];
            const float4* src = reinterpret_cast<const float4*>(g_e + row * NN);
            float4* dst = reinterpret_cast<float4*>(attn + row * NN);
            #pragma unroll
            for (int j = 0; j < 2; j++) {
                int i = tid + j * 512;             // 1024 float4 per row
                float4 v = src[i];
                v.x *= rinv; v.y *= rinv; v.z *= rinv; v.w *= rinv;
                dst[i] = v;
            }
        }
        return;
    }

    // ---------------- gemm path ----------------
    extern __shared__ float smem[];
    float* As = smem;                        // [2][128][36]
    float* Bs = smem + 2 * AS_STAGE;         // [2][32][132]

    const int b  = gid >> 6;
    const int t  = gid & 63;
    const int c0 = (t & 1) * 128;
    const int m0 = (t >> 1) * 128;

    const float* vb = g_v + (size_t)b * CC * NN;
    const float* eb = g_e + (size_t)b * NN * NN;

    const int lane = tid & 31;
    const int w    = tid >> 5;               // 0..15
    const int wc   = w >> 2;                 // 0..3 (c, x32)
    const int wm   = w & 3;                  // 0..3 (m, x32)

    const uint32_t as_base = (uint32_t)__cvta_generic_to_shared(As);
    const uint32_t bs_base = (uint32_t)__cvta_generic_to_shared(Bs);

    // staging: 512 threads, 2 cp_async16 each for A and B
    const int a_row = tid >> 2;              // 0..127
    const int a_c8  = (tid & 3) * 8;         // 0,8,16,24
    const int b_kr  = tid >> 4;              // 0..31
    const int b_m8  = (tid & 15) * 8;        // 0..120

    auto load_stage = [&](int s, int k0) {
        const float* ga = &vb[(size_t)(c0 + a_row) * NN + k0 + a_c8];
        uint32_t da = as_base + (s * AS_STAGE + a_row * AS_PITCH + a_c8) * 4;
        cp_async16(da,      ga);
        cp_async16(da + 16, ga + 4);
        const float* gb = &eb[(size_t)(k0 + b_kr) * NN + m0 + b_m8];
        uint32_t db = bs_base + (s * BS_STAGE + b_kr * BS_PITCH + b_m8) * 4;
        cp_async16(db,      gb);
        cp_async16(db + 16, gb + 4);
    };

    float acc[2][4][4];
    #pragma unroll
    for (int mi = 0; mi < 2; mi++)
        #pragma unroll
        for (int ni = 0; ni < 4; ni++)
            #pragma unroll
            for (int r = 0; r < 4; r++) acc[mi][ni][r] = 0.f;

    const int lq = lane >> 2;
    const int lr = lane & 3;

    load_stage(0, 0);
    cp_commit();

    for (int it = 0; it < NN / 32; it++) {
        const int s = it & 1;
        if (it + 1 < NN / 32) {
            load_stage(s ^ 1, (it + 1) * 32);
            cp_commit();
            cp_wait<1>();
        } else {
            cp_wait<0>();
        }
        __syncthreads();

        const float* Asl = As + s * AS_STAGE;
        const float* Bsl = Bs + s * BS_STAGE;

        #pragma unroll
        for (int kk = 0; kk < 32; kk += 8) {
            uint32_t af[2][4];
            #pragma unroll
            for (int mi = 0; mi < 2; mi++) {
                int r = wc * 32 + mi * 16 + lq;
                af[mi][0] = __float_as_uint(Asl[(r    ) * AS_PITCH + kk + lr    ]);
                af[mi][1] = __float_as_uint(Asl[(r + 8) * AS_PITCH + kk + lr    ]);
                af[mi][2] = __float_as_uint(Asl[(r    ) * AS_PITCH + kk + lr + 4]);
                af[mi][3] = __float_as_uint(Asl[(r + 8) * AS_PITCH + kk + lr + 4]);
            }
            uint32_t bf[4][2];
            #pragma unroll
            for (int ni = 0; ni < 4; ni++) {
                int m = wm * 32 + ni * 8 + lq;
                bf[ni][0] = __float_as_uint(Bsl[(kk + lr    ) * BS_PITCH + m]);
                bf[ni][1] = __float_as_uint(Bsl[(kk + lr + 4) * BS_PITCH + m]);
            }
            #pragma unroll
            for (int mi = 0; mi < 2; mi++)
                #pragma unroll
                for (int ni = 0; ni < 4; ni++)
                    mma_tf32_16x8x8(acc[mi][ni], af[mi], bf[ni]);
        }
        __syncthreads();
    }

    const float g = __ldg(gamma);
    const float* xb = x + (size_t)b * CC * NN;
    float* ob = out + (size_t)b * CC * NN;

    #pragma unroll
    for (int mi = 0; mi < 2; mi++) {
        #pragma unroll
        for (int ni = 0; ni < 4; ni++) {
            int c = c0 + wc * 32 + mi * 16 + lq;
            int m = m0 + wm * 32 + ni * 8 + lr * 2;
            {
                size_t off = (size_t)c * NN + m;
                float2 xr = *reinterpret_cast<const float2*>(&xb[off]);
                float2 o;
                o.x = g * acc[mi][ni][0] + xr.x;
                o.y = g * acc[mi][ni][1] + xr.y;
                *reinterpret_cast<float2*>(&ob[off]) = o;
            }
            {
                size_t off = (size_t)(c + 8) * NN + m;
                float2 xr = *reinterpret_cast<const float2*>(&xb[off]);
                float2 o;
                o.x = g * acc[mi][ni][2] + xr.x;
                o.y = g * acc[mi][ni][3] + xr.y;
                *reinterpret_cast<float2*>(&ob[off]) = o;
            }
        }
    }
}

// ---------------------------------------------------------------------------
extern "C" void kernel_launch(void* const* d_in, const int* in_sizes, int n_in,
                              void* d_out, int out_size)
{
    (void)in_sizes; (void)n_in; (void)out_size;

    const float* x     = (const float*)d_in[0];
    const float* Wq    = (const float*)d_in[1];
    const float* bq    = (const float*)d_in[2];
    const float* Wk    = (const float*)d_in[3];
    const float* bk    = (const float*)d_in[4];
    const float* Wv    = (const float*)d_in[5];
    const float* bv    = (const float*)d_in[6];
    const float* gamma = (const float*)d_in[7];

    float* out  = (float*)d_out;                       // (B, C, H, W)
    float* attn = out + (size_t)BB * CC * NN;          // (B, N, N)

    static bool attr_set = false;
    if (!attr_set) {
        cudaFuncSetAttribute(fat_scores_vproj,
            cudaFuncAttributeMaxDynamicSharedMemorySize, (int)SMEM_GEMM);
        cudaFuncSetAttribute(gemm_norm_fused,
            cudaFuncAttributeMaxDynamicSharedMemorySize, (int)SMEM_GEMM);
        attr_set = true;
    }

    qk_proj         <<<dim3(NN / 128, BB), 256>>>(x, Wq, bq, Wk, bk);
    fat_scores_vproj<<<256 + BB * 32 * 32, 256, SMEM_GEMM>>>(x, Wv, bv);
    stats_reduce    <<<dim3(NN / 128, BB), 128>>>();
    scale_v         <<<(BB * CC * NN / 4) / 256, 256>>>();
    gemm_norm_fused <<<512, 512, SMEM_GEMM>>>(x, gamma, out, attn);
}